// round 9
// baseline (speedup 1.0000x reference)
#include <cuda_runtime.h>
#include <cuda_bf16.h>
#include <cstdint>

// Problem constants
#define BB 4
#define SS 4096
#define DD 1024
#define MM (BB * SS)          // 16384
#define CH 256                // scan chunks per sequence
#define LL (SS / CH)          // 16 per chunk

// GEMM: Y[M, 3072] = X[M,1024] @ W[3072,1024]^T, split bf16 (hi/lo packed rows)
#define NTOT (3 * DD)         // 3072
#define CTA_M 128
#define CTA_N 128
#define KC 32                 // k elems per stage (one 128B packed chunk per row)
#define NSTG (DD / KC)        // 32 stages
#define ROWB 4096             // bytes per packed global row: 32 chunks * 128B

#define SWZ(o) ((uint32_t)(o) ^ ((((uint32_t)(o)) >> 3) & 0x70))

#define NPIPE 3
#define STAGE_BYTES 32768     // A 16KB + B 16KB
#define OFF_B 16384
#define SMEM_GEMM (NPIPE * STAGE_BYTES)   // 96 KB -> 2 CTAs/SM

// ---------------------------------------------------------------------------
// Device scratch
// ---------------------------------------------------------------------------
// packed rows: per k32 chunk, 128B = [hi: 32 bf16 | lo: 32 bf16]
__device__ __align__(128) unsigned char g_Ap[(size_t)MM * ROWB];
__device__ __align__(128) unsigned char g_Bp[(size_t)NTOT * ROWB];
__device__ float g_bufG[(size_t)MM * DD];
__device__ float g_bufV[(size_t)MM * DD];
__device__ float g_bufA[(size_t)MM * DD];
__device__ float g_cA[(size_t)BB * CH * DD];
__device__ float g_cH[(size_t)BB * CH * DD];
__device__ float g_hin[(size_t)BB * CH * DD];

// ---------------------------------------------------------------------------
// PTX helpers
// ---------------------------------------------------------------------------
__device__ __forceinline__ uint32_t smem_u32(const void* p) {
    uint32_t a;
    asm("{ .reg .u64 t; cvta.to.shared.u64 t, %1; cvt.u32.u64 %0, t; }" : "=r"(a) : "l"(p));
    return a;
}

#define CP_ASYNC16(sm, gp) \
    asm volatile("cp.async.cg.shared.global [%0], [%1], 16;" :: "r"(sm), "l"(gp))
#define CP_COMMIT() asm volatile("cp.async.commit_group;" ::: "memory")
#define CP_WAIT(N)  asm volatile("cp.async.wait_group %0;" :: "n"(N) : "memory")

#define LDSM_X4(r0, r1, r2, r3, addr) \
    asm volatile("ldmatrix.sync.aligned.m8n8.x4.shared.b16 {%0,%1,%2,%3}, [%4];" \
                 : "=r"(r0), "=r"(r1), "=r"(r2), "=r"(r3) : "r"(addr))

#define MMA_BF16(c, a, b) \
    asm volatile("mma.sync.aligned.m16n8k16.row.col.f32.bf16.bf16.f32 " \
                 "{%0,%1,%2,%3}, {%4,%5,%6,%7}, {%8,%9}, {%0,%1,%2,%3};" \
                 : "+f"((c)[0]), "+f"((c)[1]), "+f"((c)[2]), "+f"((c)[3]) \
                 : "r"((a)[0]), "r"((a)[1]), "r"((a)[2]), "r"((a)[3]), \
                   "r"((b)[0]), "r"((b)[1]))

// ---------------------------------------------------------------------------
// Split kernels: fp32 -> bf16 hi/lo into packed-row layout
// ---------------------------------------------------------------------------
__device__ __forceinline__ void split4(const float4 v, ushort4& hv, ushort4& lv)
{
    float f[4] = {v.x, v.y, v.z, v.w};
    unsigned short h[4], l[4];
#pragma unroll
    for (int q = 0; q < 4; ++q) {
        __nv_bfloat16 hb = __float2bfloat16(f[q]);
        __nv_bfloat16 lb = __float2bfloat16(f[q] - __bfloat162float(hb));
        h[q] = __bfloat16_as_ushort(hb);
        l[q] = __bfloat16_as_ushort(lb);
    }
    hv = make_ushort4(h[0], h[1], h[2], h[3]);
    lv = make_ushort4(l[0], l[1], l[2], l[3]);
}

__global__ __launch_bounds__(256)
void splitX_kernel(const float* __restrict__ x)
{
    int i = blockIdx.x * 256 + threadIdx.x;            // float4 index
    if (i >= MM * DD / 4) return;
    float4 v = reinterpret_cast<const float4*>(x)[i];
    int lin = i * 4;
    int m = lin >> 10;
    int k = lin & 1023;
    int chunk = k >> 5, pos = k & 31;
    ushort4 hv, lv;
    split4(v, hv, lv);
    size_t base = (size_t)m * ROWB + chunk * 128 + pos * 2;
    *reinterpret_cast<ushort4*>(g_Ap + base)      = hv;
    *reinterpret_cast<ushort4*>(g_Ap + base + 64) = lv;
}

// fused over the 3 weight matrices via blockIdx.y
__global__ __launch_bounds__(256)
void splitW_kernel(const float* __restrict__ wg,
                   const float* __restrict__ wv,
                   const float* __restrict__ wd)
{
    const int z = blockIdx.y;
    const float* __restrict__ w = (z == 0) ? wg : (z == 1) ? wv : wd;
    int i = blockIdx.x * 256 + threadIdx.x;
    if (i >= DD * DD / 4) return;
    float4 v = reinterpret_cast<const float4*>(w)[i];
    int lin = i * 4;
    int n = lin >> 10;
    int k = lin & 1023;
    int chunk = k >> 5, pos = k & 31;
    ushort4 hv, lv;
    split4(v, hv, lv);
    size_t base = (size_t)(z * DD + n) * ROWB + chunk * 128 + pos * 2;
    *reinterpret_cast<ushort4*>(g_Bp + base)      = hv;
    *reinterpret_cast<ushort4*>(g_Bp + base + 64) = lv;
}

// ---------------------------------------------------------------------------
// bf16 HMMA GEMM + activation epilogue (split-precision, packed hi|lo rows)
// grid (NTOT/CTA_N = 24, MM/CTA_M = 128), 256 threads, 8 warps of 32x64
// 3-stage cp.async pipeline, 1 barrier per stage, 2 CTAs/SM
// ---------------------------------------------------------------------------
__global__ __launch_bounds__(256, 2)
void gemm_hmma_kernel(const float* __restrict__ bg,
                      const float* __restrict__ bv,
                      const float* __restrict__ bd)
{
    extern __shared__ char smem[];
    const uint32_t smb = smem_u32(smem);

    const int tid  = threadIdx.x;
    const int wid  = tid >> 5;
    const int lane = tid & 31;
    const int wm = wid & 3;          // m-tile of 32 (4 tiles)
    const int wn = wid >> 2;         // n-tile of 64 (2 tiles)

    const int bn = blockIdx.x * CTA_N;
    const int bm = blockIdx.y * CTA_M;

    const unsigned char* Ab = g_Ap + (size_t)bm * ROWB;
    const unsigned char* Bb = g_Bp + (size_t)bn * ROWB;

    float acc[2][8][4];
#pragma unroll
    for (int i = 0; i < 2; ++i)
#pragma unroll
        for (int j = 0; j < 8; ++j)
#pragma unroll
            for (int q = 0; q < 4; ++q) acc[i][j][q] = 0.0f;

    // prefetch k-chunk c into pipeline slot
    auto prefetch = [&](int c, int slot) {
        const uint32_t stA = smb + slot * STAGE_BYTES;
        const uint32_t stB = stA + OFF_B;
#pragma unroll
        for (int it = 0; it < 4; ++it) {
            int u = tid + it * 256;
            int row = u >> 3, blk = u & 7;
            CP_ASYNC16(stA + SWZ(row * 128 + blk * 16),
                       Ab + (size_t)row * ROWB + c * 128 + blk * 16);
        }
#pragma unroll
        for (int it = 0; it < 4; ++it) {
            int u = tid + it * 256;
            int row = u >> 3, blk = u & 7;
            CP_ASYNC16(stB + SWZ(row * 128 + blk * 16),
                       Bb + (size_t)row * ROWB + c * 128 + blk * 16);
        }
        CP_COMMIT();
    };

    prefetch(0, 0);
    prefetch(1, 1);

    for (int c = 0; c < NSTG; ++c) {
        const int slot = c % NPIPE;
        if (c == NSTG - 1) { CP_WAIT(0); } else { CP_WAIT(1); }
        __syncthreads();                      // stage c visible; slot (c+2)%3 free
        if (c + 2 < NSTG) prefetch(c + 2, (c + 2) % NPIPE);

        const uint32_t stA = smb + slot * STAGE_BYTES;
        const uint32_t stB = stA + OFF_B;

#pragma unroll
        for (int ks = 0; ks < 2; ++ks) {       // two k16 steps per k32 chunk
            uint32_t ah[2][4], al[2][4];
#pragma unroll
            for (int mi = 0; mi < 2; ++mi) {
                int rowA = wm * 32 + mi * 16 + (lane & 15);
                uint32_t base = rowA * 128 + ks * 32 + ((lane >> 4) << 4);
                LDSM_X4(ah[mi][0], ah[mi][1], ah[mi][2], ah[mi][3], stA + SWZ(base));
                LDSM_X4(al[mi][0], al[mi][1], al[mi][2], al[mi][3], stA + SWZ(base + 64));
            }
            uint32_t bh[8][2];
#pragma unroll
            for (int p = 0; p < 4; ++p) {
                int nrow = wn * 64 + p * 16 + (lane & 7) + ((lane >> 4) << 3);
                uint32_t base = nrow * 128 + ks * 32 + (((lane >> 3) & 1) << 4);
                uint32_t r0, r1, r2, r3;
                LDSM_X4(r0, r1, r2, r3, stB + SWZ(base));
                bh[2 * p][0] = r0; bh[2 * p][1] = r1;
                bh[2 * p + 1][0] = r2; bh[2 * p + 1][1] = r3;
            }
#pragma unroll
            for (int mi = 0; mi < 2; ++mi)
#pragma unroll
                for (int ni = 0; ni < 8; ++ni) {
                    MMA_BF16(acc[mi][ni], ah[mi], bh[ni]);
                    MMA_BF16(acc[mi][ni], al[mi], bh[ni]);
                }
#pragma unroll
            for (int p = 0; p < 4; ++p) {
                int nrow = wn * 64 + p * 16 + (lane & 7) + ((lane >> 4) << 3);
                uint32_t base = nrow * 128 + ks * 32 + (((lane >> 3) & 1) << 4);
                uint32_t r0, r1, r2, r3;
                LDSM_X4(r0, r1, r2, r3, stB + SWZ(base + 64));
                bh[2 * p][0] = r0; bh[2 * p][1] = r1;
                bh[2 * p + 1][0] = r2; bh[2 * p + 1][1] = r3;
            }
#pragma unroll
            for (int mi = 0; mi < 2; ++mi)
#pragma unroll
                for (int ni = 0; ni < 8; ++ni)
                    MMA_BF16(acc[mi][ni], ah[mi], bh[ni]);
        }
    }

    // Epilogue: bias + activation, write fp32
    const int z = blockIdx.x >> 3;          // 24 x-CTAs: 8 per output
    const int nloc = bn & 1023;
    const float* bias = (z == 0) ? bg : (z == 1) ? bv : bd;
    float* outp = (z == 0) ? g_bufG : (z == 1) ? g_bufV : g_bufA;

#pragma unroll
    for (int mi = 0; mi < 2; ++mi) {
#pragma unroll
        for (int ni = 0; ni < 8; ++ni) {
            int row0 = bm + wm * 32 + mi * 16 + (lane >> 2);
            int col  = nloc + wn * 64 + ni * 8 + (lane & 3) * 2;
            float b0 = bias[col], b1 = bias[col + 1];
#pragma unroll
            for (int half = 0; half < 2; ++half) {
                int row = row0 + half * 8;
                float v0 = acc[mi][ni][half * 2 + 0] + b0;
                float v1 = acc[mi][ni][half * 2 + 1] + b1;
                float r0, r1;
                if (z == 0) {
                    r0 = 1.0f / (1.0f + __expf(-v0));
                    r1 = 1.0f / (1.0f + __expf(-v1));
                } else if (z == 1) {
                    r0 = tanhf(v0);
                    r1 = tanhf(v1);
                } else {
                    r0 = 0.001f + 0.998f / (1.0f + __expf(-v0));
                    r1 = 0.001f + 0.998f / (1.0f + __expf(-v1));
                }
                float2 o2; o2.x = r0; o2.y = r1;
                *reinterpret_cast<float2*>(outp + (size_t)row * DD + col) = o2;
            }
        }
    }
}

// ---------------------------------------------------------------------------
// Scan passes — float4 per thread, CH=256 chunks -> grid 1024 CTAs
// ---------------------------------------------------------------------------
__global__ __launch_bounds__(256)
void scan_pass1_kernel()
{
    const int d4 = threadIdx.x;          // 256 threads * 4 = 1024 d
    const int c = blockIdx.x;
    const int b = blockIdx.y;

    size_t base = (((size_t)(b * SS + c * LL)) * DD + d4 * 4) >> 2;  // float4 index
    const float4* A4 = reinterpret_cast<const float4*>(g_bufA);
    const float4* G4 = reinterpret_cast<const float4*>(g_bufG);
    const float4* V4 = reinterpret_cast<const float4*>(g_bufV);

    float4 Ap = make_float4(1.f, 1.f, 1.f, 1.f);
    float4 h  = make_float4(0.f, 0.f, 0.f, 0.f);
#pragma unroll 4
    for (int s = 0; s < LL; ++s) {
        float4 a = A4[base];
        float4 g = G4[base];
        float4 v = V4[base];
        Ap.x *= a.x; Ap.y *= a.y; Ap.z *= a.z; Ap.w *= a.w;
        h.x = fmaf(a.x, h.x, g.x * v.x);
        h.y = fmaf(a.y, h.y, g.y * v.y);
        h.z = fmaf(a.z, h.z, g.z * v.z);
        h.w = fmaf(a.w, h.w, g.w * v.w);
        base += DD / 4;
    }
    const size_t ci = ((size_t)(b * CH + c) * DD + d4 * 4) >> 2;
    reinterpret_cast<float4*>(g_cA)[ci] = Ap;
    reinterpret_cast<float4*>(g_cH)[ci] = h;
}

__global__ __launch_bounds__(256)
void scan_pass2_kernel()
{
    const int d4 = threadIdx.x;
    const int b = blockIdx.x;

    const float4* cA4 = reinterpret_cast<const float4*>(g_cA);
    const float4* cH4 = reinterpret_cast<const float4*>(g_cH);
    float4* hin4 = reinterpret_cast<float4*>(g_hin);

    float4 h = make_float4(0.f, 0.f, 0.f, 0.f);
#pragma unroll 4
    for (int c = 0; c < CH; ++c) {
        const size_t ci = ((size_t)(b * CH + c) * DD + d4 * 4) >> 2;
        hin4[ci] = h;
        float4 A = cA4[ci];
        float4 H = cH4[ci];
        h.x = fmaf(A.x, h.x, H.x);
        h.y = fmaf(A.y, h.y, H.y);
        h.z = fmaf(A.z, h.z, H.z);
        h.w = fmaf(A.w, h.w, H.w);
    }
}

__global__ __launch_bounds__(256)
void scan_pass3_kernel(float* __restrict__ out)
{
    const int d4 = threadIdx.x;
    const int c = blockIdx.x;
    const int b = blockIdx.y;

    size_t base = (((size_t)(b * SS + c * LL)) * DD + d4 * 4) >> 2;
    const float4* A4 = reinterpret_cast<const float4*>(g_bufA);
    const float4* G4 = reinterpret_cast<const float4*>(g_bufG);
    const float4* V4 = reinterpret_cast<const float4*>(g_bufV);
    float4* O4 = reinterpret_cast<float4*>(out);

    float4 h = reinterpret_cast<const float4*>(g_hin)[((size_t)(b * CH + c) * DD + d4 * 4) >> 2];
#pragma unroll 4
    for (int s = 0; s < LL; ++s) {
        float4 a = A4[base];
        float4 g = G4[base];
        float4 v = V4[base];
        h.x = fmaf(a.x, h.x, g.x * v.x);
        h.y = fmaf(a.y, h.y, g.y * v.y);
        h.z = fmaf(a.z, h.z, g.z * v.z);
        h.w = fmaf(a.w, h.w, g.w * v.w);
        O4[base] = h;
        base += DD / 4;
    }
}

// ---------------------------------------------------------------------------
// Launch
// ---------------------------------------------------------------------------
extern "C" void kernel_launch(void* const* d_in, const int* in_sizes, int n_in,
                              void* d_out, int out_size)
{
    const float* x  = (const float*)d_in[0];
    const float* Wg = (const float*)d_in[1];
    const float* bg = (const float*)d_in[2];
    const float* Wv = (const float*)d_in[3];
    const float* bv = (const float*)d_in[4];
    const float* Wd = (const float*)d_in[5];
    const float* bd = (const float*)d_in[6];
    float* out = (float*)d_out;

    cudaFuncSetAttribute(gemm_hmma_kernel,
                         cudaFuncAttributeMaxDynamicSharedMemorySize, SMEM_GEMM);

    splitX_kernel<<<(MM * DD / 4 + 255) / 256, 256>>>(x);
    splitW_kernel<<<dim3((DD * DD / 4 + 255) / 256, 3), 256>>>(Wg, Wv, Wd);

    gemm_hmma_kernel<<<dim3(NTOT / CTA_N, MM / CTA_M), 256, SMEM_GEMM>>>(bg, bv, bd);

    scan_pass1_kernel<<<dim3(CH, BB), 256>>>();
    scan_pass2_kernel<<<BB, 256>>>();
    scan_pass3_kernel<<<dim3(CH, BB), 256>>>(out);
}

// round 10
// speedup vs baseline: 1.0689x; 1.0689x over previous
#include <cuda_runtime.h>
#include <cuda_bf16.h>
#include <cstdint>

// Problem constants
#define BB 4
#define SS 4096
#define DD 1024
#define MM (BB * SS)          // 16384
#define CH 256                // scan chunks per sequence
#define LL (SS / CH)          // 16 per chunk
#define NSUP 16               // super-chunks (16 chunks each)
#define SUBS (CH / NSUP)      // 16

// GEMM: Y[M, 3072] = X[M,1024] @ W[3072,1024]^T, split bf16 (hi/lo packed rows)
#define NTOT (3 * DD)         // 3072
#define CTA_M 128
#define CTA_N 128
#define KC 32                 // k elems per stage (one 128B packed chunk per row)
#define NSTG (DD / KC)        // 32 stages
#define ROWB 4096             // bytes per packed global row: 32 chunks * 128B

#define SWZ(o) ((uint32_t)(o) ^ ((((uint32_t)(o)) >> 3) & 0x70))

#define NPIPE 3
#define STAGE_BYTES 32768     // A 16KB + B 16KB
#define OFF_B 16384
#define SMEM_GEMM (NPIPE * STAGE_BYTES)   // 96 KB -> 2 CTAs/SM

// ---------------------------------------------------------------------------
// Device scratch
// ---------------------------------------------------------------------------
// packed rows: per k32 chunk, 128B = [hi: 32 bf16 | lo: 32 bf16]
__device__ __align__(128) unsigned char g_Ap[(size_t)MM * ROWB];
__device__ __align__(128) unsigned char g_Bp[(size_t)NTOT * ROWB];
__device__ float g_bufG[(size_t)MM * DD];
__device__ float g_bufV[(size_t)MM * DD];
__device__ float g_bufA[(size_t)MM * DD];
__device__ float g_cA[(size_t)BB * CH * DD];
__device__ float g_cH[(size_t)BB * CH * DD];
__device__ float g_hinloc[(size_t)BB * CH * DD];
__device__ float g_apre[(size_t)BB * CH * DD];
__device__ float g_sA[(size_t)BB * NSUP * DD];
__device__ float g_sH[(size_t)BB * NSUP * DD];
__device__ float g_scar[(size_t)BB * NSUP * DD];

// ---------------------------------------------------------------------------
// PTX helpers
// ---------------------------------------------------------------------------
__device__ __forceinline__ uint32_t smem_u32(const void* p) {
    uint32_t a;
    asm("{ .reg .u64 t; cvta.to.shared.u64 t, %1; cvt.u32.u64 %0, t; }" : "=r"(a) : "l"(p));
    return a;
}

#define CP_ASYNC16(sm, gp) \
    asm volatile("cp.async.cg.shared.global [%0], [%1], 16;" :: "r"(sm), "l"(gp))
#define CP_COMMIT() asm volatile("cp.async.commit_group;" ::: "memory")
#define CP_WAIT(N)  asm volatile("cp.async.wait_group %0;" :: "n"(N) : "memory")

#define LDSM_X4(r0, r1, r2, r3, addr) \
    asm volatile("ldmatrix.sync.aligned.m8n8.x4.shared.b16 {%0,%1,%2,%3}, [%4];" \
                 : "=r"(r0), "=r"(r1), "=r"(r2), "=r"(r3) : "r"(addr))

#define MMA_BF16(c, a, b) \
    asm volatile("mma.sync.aligned.m16n8k16.row.col.f32.bf16.bf16.f32 " \
                 "{%0,%1,%2,%3}, {%4,%5,%6,%7}, {%8,%9}, {%0,%1,%2,%3};" \
                 : "+f"((c)[0]), "+f"((c)[1]), "+f"((c)[2]), "+f"((c)[3]) \
                 : "r"((a)[0]), "r"((a)[1]), "r"((a)[2]), "r"((a)[3]), \
                   "r"((b)[0]), "r"((b)[1]))

// ---------------------------------------------------------------------------
// Split kernels: fp32 -> bf16 hi/lo into packed-row layout
// ---------------------------------------------------------------------------
__device__ __forceinline__ void split4(const float4 v, ushort4& hv, ushort4& lv)
{
    float f[4] = {v.x, v.y, v.z, v.w};
    unsigned short h[4], l[4];
#pragma unroll
    for (int q = 0; q < 4; ++q) {
        __nv_bfloat16 hb = __float2bfloat16(f[q]);
        __nv_bfloat16 lb = __float2bfloat16(f[q] - __bfloat162float(hb));
        h[q] = __bfloat16_as_ushort(hb);
        l[q] = __bfloat16_as_ushort(lb);
    }
    hv = make_ushort4(h[0], h[1], h[2], h[3]);
    lv = make_ushort4(l[0], l[1], l[2], l[3]);
}

__global__ __launch_bounds__(256)
void splitX_kernel(const float* __restrict__ x)
{
    int i = blockIdx.x * 256 + threadIdx.x;            // float4 index
    if (i >= MM * DD / 4) return;
    float4 v = reinterpret_cast<const float4*>(x)[i];
    int lin = i * 4;
    int m = lin >> 10;
    int k = lin & 1023;
    int chunk = k >> 5, pos = k & 31;
    ushort4 hv, lv;
    split4(v, hv, lv);
    size_t base = (size_t)m * ROWB + chunk * 128 + pos * 2;
    *reinterpret_cast<ushort4*>(g_Ap + base)      = hv;
    *reinterpret_cast<ushort4*>(g_Ap + base + 64) = lv;
}

__global__ __launch_bounds__(256)
void splitW_kernel(const float* __restrict__ wg,
                   const float* __restrict__ wv,
                   const float* __restrict__ wd)
{
    const int z = blockIdx.y;
    const float* __restrict__ w = (z == 0) ? wg : (z == 1) ? wv : wd;
    int i = blockIdx.x * 256 + threadIdx.x;
    if (i >= DD * DD / 4) return;
    float4 v = reinterpret_cast<const float4*>(w)[i];
    int lin = i * 4;
    int n = lin >> 10;
    int k = lin & 1023;
    int chunk = k >> 5, pos = k & 31;
    ushort4 hv, lv;
    split4(v, hv, lv);
    size_t base = (size_t)(z * DD + n) * ROWB + chunk * 128 + pos * 2;
    *reinterpret_cast<ushort4*>(g_Bp + base)      = hv;
    *reinterpret_cast<ushort4*>(g_Bp + base + 64) = lv;
}

// ---------------------------------------------------------------------------
// bf16 HMMA GEMM + activation epilogue (UNCHANGED from measured-best)
// ---------------------------------------------------------------------------
__global__ __launch_bounds__(256, 2)
void gemm_hmma_kernel(const float* __restrict__ bg,
                      const float* __restrict__ bv,
                      const float* __restrict__ bd)
{
    extern __shared__ char smem[];
    const uint32_t smb = smem_u32(smem);

    const int tid  = threadIdx.x;
    const int wid  = tid >> 5;
    const int lane = tid & 31;
    const int wm = wid & 3;
    const int wn = wid >> 2;

    const int bn = blockIdx.x * CTA_N;
    const int bm = blockIdx.y * CTA_M;

    const unsigned char* Ab = g_Ap + (size_t)bm * ROWB;
    const unsigned char* Bb = g_Bp + (size_t)bn * ROWB;

    float acc[2][8][4];
#pragma unroll
    for (int i = 0; i < 2; ++i)
#pragma unroll
        for (int j = 0; j < 8; ++j)
#pragma unroll
            for (int q = 0; q < 4; ++q) acc[i][j][q] = 0.0f;

    auto prefetch = [&](int c, int slot) {
        const uint32_t stA = smb + slot * STAGE_BYTES;
        const uint32_t stB = stA + OFF_B;
#pragma unroll
        for (int it = 0; it < 4; ++it) {
            int u = tid + it * 256;
            int row = u >> 3, blk = u & 7;
            CP_ASYNC16(stA + SWZ(row * 128 + blk * 16),
                       Ab + (size_t)row * ROWB + c * 128 + blk * 16);
        }
#pragma unroll
        for (int it = 0; it < 4; ++it) {
            int u = tid + it * 256;
            int row = u >> 3, blk = u & 7;
            CP_ASYNC16(stB + SWZ(row * 128 + blk * 16),
                       Bb + (size_t)row * ROWB + c * 128 + blk * 16);
        }
        CP_COMMIT();
    };

    prefetch(0, 0);
    prefetch(1, 1);

    for (int c = 0; c < NSTG; ++c) {
        const int slot = c % NPIPE;
        if (c == NSTG - 1) { CP_WAIT(0); } else { CP_WAIT(1); }
        __syncthreads();
        if (c + 2 < NSTG) prefetch(c + 2, (c + 2) % NPIPE);

        const uint32_t stA = smb + slot * STAGE_BYTES;
        const uint32_t stB = stA + OFF_B;

#pragma unroll
        for (int ks = 0; ks < 2; ++ks) {
            uint32_t ah[2][4], al[2][4];
#pragma unroll
            for (int mi = 0; mi < 2; ++mi) {
                int rowA = wm * 32 + mi * 16 + (lane & 15);
                uint32_t base = rowA * 128 + ks * 32 + ((lane >> 4) << 4);
                LDSM_X4(ah[mi][0], ah[mi][1], ah[mi][2], ah[mi][3], stA + SWZ(base));
                LDSM_X4(al[mi][0], al[mi][1], al[mi][2], al[mi][3], stA + SWZ(base + 64));
            }
            uint32_t bh[8][2];
#pragma unroll
            for (int p = 0; p < 4; ++p) {
                int nrow = wn * 64 + p * 16 + (lane & 7) + ((lane >> 4) << 3);
                uint32_t base = nrow * 128 + ks * 32 + (((lane >> 3) & 1) << 4);
                uint32_t r0, r1, r2, r3;
                LDSM_X4(r0, r1, r2, r3, stB + SWZ(base));
                bh[2 * p][0] = r0; bh[2 * p][1] = r1;
                bh[2 * p + 1][0] = r2; bh[2 * p + 1][1] = r3;
            }
#pragma unroll
            for (int mi = 0; mi < 2; ++mi)
#pragma unroll
                for (int ni = 0; ni < 8; ++ni) {
                    MMA_BF16(acc[mi][ni], ah[mi], bh[ni]);
                    MMA_BF16(acc[mi][ni], al[mi], bh[ni]);
                }
#pragma unroll
            for (int p = 0; p < 4; ++p) {
                int nrow = wn * 64 + p * 16 + (lane & 7) + ((lane >> 4) << 3);
                uint32_t base = nrow * 128 + ks * 32 + (((lane >> 3) & 1) << 4);
                uint32_t r0, r1, r2, r3;
                LDSM_X4(r0, r1, r2, r3, stB + SWZ(base + 64));
                bh[2 * p][0] = r0; bh[2 * p][1] = r1;
                bh[2 * p + 1][0] = r2; bh[2 * p + 1][1] = r3;
            }
#pragma unroll
            for (int mi = 0; mi < 2; ++mi)
#pragma unroll
                for (int ni = 0; ni < 8; ++ni)
                    MMA_BF16(acc[mi][ni], ah[mi], bh[ni]);
        }
    }

    const int z = blockIdx.x >> 3;
    const int nloc = bn & 1023;
    const float* bias = (z == 0) ? bg : (z == 1) ? bv : bd;
    float* outp = (z == 0) ? g_bufG : (z == 1) ? g_bufV : g_bufA;

#pragma unroll
    for (int mi = 0; mi < 2; ++mi) {
#pragma unroll
        for (int ni = 0; ni < 8; ++ni) {
            int row0 = bm + wm * 32 + mi * 16 + (lane >> 2);
            int col  = nloc + wn * 64 + ni * 8 + (lane & 3) * 2;
            float b0 = bias[col], b1 = bias[col + 1];
#pragma unroll
            for (int half = 0; half < 2; ++half) {
                int row = row0 + half * 8;
                float v0 = acc[mi][ni][half * 2 + 0] + b0;
                float v1 = acc[mi][ni][half * 2 + 1] + b1;
                float r0, r1;
                if (z == 0) {
                    r0 = 1.0f / (1.0f + __expf(-v0));
                    r1 = 1.0f / (1.0f + __expf(-v1));
                } else if (z == 1) {
                    r0 = tanhf(v0);
                    r1 = tanhf(v1);
                } else {
                    r0 = 0.001f + 0.998f / (1.0f + __expf(-v0));
                    r1 = 0.001f + 0.998f / (1.0f + __expf(-v1));
                }
                float2 o2; o2.x = r0; o2.y = r1;
                *reinterpret_cast<float2*>(outp + (size_t)row * DD + col) = o2;
            }
        }
    }
}

// ---------------------------------------------------------------------------
// Scan passes — float4, CH=256 chunks, hierarchical carry
// ---------------------------------------------------------------------------
__global__ __launch_bounds__(256)
void scan_pass1_kernel()
{
    const int d4 = threadIdx.x;
    const int c = blockIdx.x;
    const int b = blockIdx.y;

    size_t base = (((size_t)(b * SS + c * LL)) * DD + d4 * 4) >> 2;
    const float4* A4 = reinterpret_cast<const float4*>(g_bufA);
    const float4* G4 = reinterpret_cast<const float4*>(g_bufG);
    const float4* V4 = reinterpret_cast<const float4*>(g_bufV);

    float4 Ap = make_float4(1.f, 1.f, 1.f, 1.f);
    float4 h  = make_float4(0.f, 0.f, 0.f, 0.f);
#pragma unroll 4
    for (int s = 0; s < LL; ++s) {
        float4 a = A4[base];
        float4 g = G4[base];
        float4 v = V4[base];
        Ap.x *= a.x; Ap.y *= a.y; Ap.z *= a.z; Ap.w *= a.w;
        h.x = fmaf(a.x, h.x, g.x * v.x);
        h.y = fmaf(a.y, h.y, g.y * v.y);
        h.z = fmaf(a.z, h.z, g.z * v.z);
        h.w = fmaf(a.w, h.w, g.w * v.w);
        base += DD / 4;
    }
    const size_t ci = ((size_t)(b * CH + c) * DD + d4 * 4) >> 2;
    reinterpret_cast<float4*>(g_cA)[ci] = Ap;
    reinterpret_cast<float4*>(g_cH)[ci] = h;
}

// pass2a: per super-chunk local scan of sub-chunk summaries
// grid (NSUP, BB), 256 threads
__global__ __launch_bounds__(256)
void scan_pass2a_kernel()
{
    const int d4 = threadIdx.x;
    const int s = blockIdx.x;
    const int b = blockIdx.y;

    const float4* cA4 = reinterpret_cast<const float4*>(g_cA);
    const float4* cH4 = reinterpret_cast<const float4*>(g_cH);
    float4* hinloc4 = reinterpret_cast<float4*>(g_hinloc);
    float4* apre4   = reinterpret_cast<float4*>(g_apre);

    float4 h = make_float4(0.f, 0.f, 0.f, 0.f);
    float4 p = make_float4(1.f, 1.f, 1.f, 1.f);
#pragma unroll 4
    for (int c16 = 0; c16 < SUBS; ++c16) {
        const int chunk = s * SUBS + c16;
        const size_t ci = ((size_t)(b * CH + chunk) * DD + d4 * 4) >> 2;
        hinloc4[ci] = h;
        apre4[ci] = p;
        float4 A = cA4[ci];
        float4 H = cH4[ci];
        h.x = fmaf(A.x, h.x, H.x);
        h.y = fmaf(A.y, h.y, H.y);
        h.z = fmaf(A.z, h.z, H.z);
        h.w = fmaf(A.w, h.w, H.w);
        p.x *= A.x; p.y *= A.y; p.z *= A.z; p.w *= A.w;
    }
    const size_t si = ((size_t)(b * NSUP + s) * DD + d4 * 4) >> 2;
    reinterpret_cast<float4*>(g_sA)[si] = p;
    reinterpret_cast<float4*>(g_sH)[si] = h;
}

// pass2b: scan super summaries -> super carries
// grid (BB), 256 threads
__global__ __launch_bounds__(256)
void scan_pass2b_kernel()
{
    const int d4 = threadIdx.x;
    const int b = blockIdx.x;

    const float4* sA4 = reinterpret_cast<const float4*>(g_sA);
    const float4* sH4 = reinterpret_cast<const float4*>(g_sH);
    float4* scar4 = reinterpret_cast<float4*>(g_scar);

    float4 h = make_float4(0.f, 0.f, 0.f, 0.f);
#pragma unroll
    for (int s = 0; s < NSUP; ++s) {
        const size_t si = ((size_t)(b * NSUP + s) * DD + d4 * 4) >> 2;
        scar4[si] = h;
        float4 A = sA4[si];
        float4 H = sH4[si];
        h.x = fmaf(A.x, h.x, H.x);
        h.y = fmaf(A.y, h.y, H.y);
        h.z = fmaf(A.z, h.z, H.z);
        h.w = fmaf(A.w, h.w, H.w);
    }
}

__global__ __launch_bounds__(256)
void scan_pass3_kernel(float* __restrict__ out)
{
    const int d4 = threadIdx.x;
    const int c = blockIdx.x;
    const int b = blockIdx.y;
    const int sup = c / SUBS;

    size_t base = (((size_t)(b * SS + c * LL)) * DD + d4 * 4) >> 2;
    const float4* A4 = reinterpret_cast<const float4*>(g_bufA);
    const float4* G4 = reinterpret_cast<const float4*>(g_bufG);
    const float4* V4 = reinterpret_cast<const float4*>(g_bufV);
    float4* O4 = reinterpret_cast<float4*>(out);

    const size_t ci = ((size_t)(b * CH + c) * DD + d4 * 4) >> 2;
    const size_t si = ((size_t)(b * NSUP + sup) * DD + d4 * 4) >> 2;
    float4 hl = reinterpret_cast<const float4*>(g_hinloc)[ci];
    float4 ap = reinterpret_cast<const float4*>(g_apre)[ci];
    float4 sc = reinterpret_cast<const float4*>(g_scar)[si];
    float4 h;
    h.x = fmaf(ap.x, sc.x, hl.x);
    h.y = fmaf(ap.y, sc.y, hl.y);
    h.z = fmaf(ap.z, sc.z, hl.z);
    h.w = fmaf(ap.w, sc.w, hl.w);

#pragma unroll 4
    for (int s = 0; s < LL; ++s) {
        float4 a = A4[base];
        float4 g = G4[base];
        float4 v = V4[base];
        h.x = fmaf(a.x, h.x, g.x * v.x);
        h.y = fmaf(a.y, h.y, g.y * v.y);
        h.z = fmaf(a.z, h.z, g.z * v.z);
        h.w = fmaf(a.w, h.w, g.w * v.w);
        O4[base] = h;
        base += DD / 4;
    }
}

// ---------------------------------------------------------------------------
// Launch
// ---------------------------------------------------------------------------
extern "C" void kernel_launch(void* const* d_in, const int* in_sizes, int n_in,
                              void* d_out, int out_size)
{
    const float* x  = (const float*)d_in[0];
    const float* Wg = (const float*)d_in[1];
    const float* bg = (const float*)d_in[2];
    const float* Wv = (const float*)d_in[3];
    const float* bv = (const float*)d_in[4];
    const float* Wd = (const float*)d_in[5];
    const float* bd = (const float*)d_in[6];
    float* out = (float*)d_out;

    cudaFuncSetAttribute(gemm_hmma_kernel,
                         cudaFuncAttributeMaxDynamicSharedMemorySize, SMEM_GEMM);

    splitX_kernel<<<(MM * DD / 4 + 255) / 256, 256>>>(x);
    splitW_kernel<<<dim3((DD * DD / 4 + 255) / 256, 3), 256>>>(Wg, Wv, Wd);

    gemm_hmma_kernel<<<dim3(NTOT / CTA_N, MM / CTA_M), 256, SMEM_GEMM>>>(bg, bv, bd);

    scan_pass1_kernel<<<dim3(CH, BB), 256>>>();
    scan_pass2a_kernel<<<dim3(NSUP, BB), 256>>>();
    scan_pass2b_kernel<<<BB, 256>>>();
    scan_pass3_kernel<<<dim3(CH, BB), 256>>>(out);
}